// round 14
// baseline (speedup 1.0000x reference)
#include <cuda_runtime.h>
#include <cuda_fp16.h>
#include <cstdint>
#include <math.h>
#include <float.h>

#define N_NODES 50000
#define N_EDGES 600000
#define NHID    128
#define NGRAPH  512
#define NCLS    10
#define NPART   ((N_NODES + 255) / 256)   // 196
#define WROW    136
#define WTILE   (128 * WROW)
#define AROW    68
#define ATILE16 (64 * AROW)
#define NB_GT   ((N_NODES + 63) / 64)      // 782 M tiles
#define GEMM_GRID 296

// ---------------- scratch ----------------
__device__ __half2  g_x16[N_NODES * 64];
__device__ __half2  g_xw2[N_NODES * 64];
__device__ __half2  g_h16[N_NODES * 64];
__device__ float    g_dinv[N_NODES];
__device__ int      g_deg [N_NODES];
__device__ int      g_beg [N_NODES];
__device__ int      g_fill[N_NODES];
__device__ int      g_total;
__device__ int2     g_epack[N_EDGES];
__device__ int      g_gptr[NGRAPH + 1];
__device__ float    g_pool[NGRAPH * NHID];
__device__ uint32_t g_wprep[3 * WTILE];

// ---------------- graph preprocessing ----------------
__global__ void zero_kernel() {
    int v = blockIdx.x * blockDim.x + threadIdx.x;
    if (v < N_NODES) g_deg[v] = 0;
    if (v == 0) g_total = 0;
}

__global__ void deg_kernel(const int* __restrict__ dst) {
    int e = blockIdx.x * blockDim.x + threadIdx.x;
    if (e < N_EDGES) atomicAdd(&g_deg[dst[e]], 1);
}

__global__ void __launch_bounds__(256) scanfill_kernel() {
    int i = blockIdx.x * 256 + threadIdx.x;
    int v = 0;
    if (i < N_NODES) {
        v = g_deg[i];
        g_dinv[i] = rsqrtf((float)v + 1.0f);
    }
    int lane = threadIdx.x & 31, w = threadIdx.x >> 5;
    int x = v;
    for (int o = 1; o < 32; o <<= 1) {
        int n = __shfl_up_sync(~0u, x, o);
        if (lane >= o) x += n;
    }
    __shared__ int ws[8];
    __shared__ int sbase;
    if (lane == 31) ws[w] = x;
    __syncthreads();
    if (w == 0 && lane < 8) {
        int s = ws[lane];
        for (int o = 1; o < 8; o <<= 1) {
            int n = __shfl_up_sync(0xffu, s, o);
            if (lane >= o) s += n;
        }
        ws[lane] = s;
    }
    __syncthreads();
    if (threadIdx.x == 0) sbase = atomicAdd(&g_total, ws[7]);
    __syncthreads();
    int off = x - v + ((w > 0) ? ws[w - 1] : 0) + sbase;
    if (i < N_NODES) {
        g_beg[i]  = off;
        g_fill[i] = off;
    }
}

__global__ void fill_kernel(const int* __restrict__ src, const int* __restrict__ dst) {
    int e = blockIdx.x * blockDim.x + threadIdx.x;
    if (e >= N_EDGES) return;
    int d = dst[e];
    int s = src[e];
    int pos = atomicAdd(&g_fill[d], 1);
    g_epack[pos] = make_int2(s, __float_as_int(g_dinv[s] * g_dinv[d]));
}

// ---------------- x -> fp16 ----------------
__global__ void __launch_bounds__(256) x16_kernel(const float* __restrict__ x) {
    int idx = blockIdx.x * 256 + threadIdx.x;
    if (idx < N_NODES * 64) {
        float2 f = ((const float2*)x)[idx];
        g_x16[idx] = __floats2half2_rn(f.x, f.y);
    }
}

// ---------------- fp16 split helpers ----------------
__device__ __forceinline__ uint32_t packh_hi(float a, float b, float& ra, float& rb) {
    __half h0 = __float2half_rn(a);
    __half h1 = __float2half_rn(b);
    ra = a - __half2float(h0);
    rb = b - __half2float(h1);
    __half2 p = __half2(h0, h1);
    return *(uint32_t*)&p;
}
__device__ __forceinline__ uint32_t packh_lo(float ra, float rb) {
    __half2 p = __half2(__float2half_rn(ra), __float2half_rn(rb));
    return *(uint32_t*)&p;
}
#define MMA_F16(C, A0, A1, A2, A3, B0, B1)                                         \
    asm volatile("mma.sync.aligned.m16n8k16.row.col.f32.f16.f16.f32 "              \
                 "{%0,%1,%2,%3}, {%4,%5,%6,%7}, {%8,%9}, {%0,%1,%2,%3};"           \
                 : "+f"(C[0]), "+f"(C[1]), "+f"(C[2]), "+f"(C[3])                  \
                 : "r"(A0), "r"(A1), "r"(A2), "r"(A3), "r"(B0), "r"(B1))

// ---------------- W pre-split ----------------
__global__ void __launch_bounds__(256) wsplit_kernel(const float* __restrict__ W1,
                                                     const float* __restrict__ W2,
                                                     const float* __restrict__ W3) {
    const float* W = (blockIdx.y == 0) ? W1 : (blockIdx.y == 1) ? W2 : W3;
    uint32_t* dst = g_wprep + blockIdx.y * WTILE;
    int base = blockIdx.x * 256 + threadIdx.x;
    for (int p = base; p < 4096; p += 2048) {
        int kp = p >> 6;
        int np = p & 63;
        int k = kp * 2, n = np * 2;
        float2 w0 = *(const float2*)(W + k * 128 + n);
        float2 w1 = *(const float2*)(W + (k + 1) * 128 + n);
        float r0, r1, r2, r3;
        uint32_t hA = packh_hi(w0.x, w1.x, r0, r1);
        uint32_t hB = packh_hi(w0.y, w1.y, r2, r3);
        *(uint2*)&dst[n * WROW + kp * 2]       = make_uint2(hA, packh_lo(r0, r1));
        *(uint2*)&dst[(n + 1) * WROW + kp * 2] = make_uint2(hB, packh_lo(r2, r3));
    }
}

// ---------------- persistent tensor-core GEMM, A double-buffered ----------------
__global__ void __launch_bounds__(256, 2) gemm_tc(int use_gh, int layer) {
    extern __shared__ uint32_t sm[];
    uint32_t* Abuf0 = sm;
    uint32_t* Abuf1 = sm + ATILE16;
    uint32_t* Wt    = sm + 2 * ATILE16;
    const uint4* A4 = use_gh ? (const uint4*)g_h16 : (const uint4*)g_x16;
    const int tid = threadIdx.x;

    {
        const uint4* wp = (const uint4*)(g_wprep + layer * WTILE);
        uint4* Wt4 = (uint4*)Wt;
#pragma unroll
        for (int it = 0; it < 17; it++) {
            int idx = it * 256 + tid;
            if (idx < WTILE / 4) Wt4[idx] = wp[idx];
        }
    }
    {
        const int m0 = blockIdx.x * 64;
        uint4* As4 = (uint4*)Abuf0;
#pragma unroll
        for (int it = 0; it < 4; it++) {
            int idx = it * 256 + tid;
            int r   = idx >> 4;
            int c4  = idx & 15;
            int gr  = m0 + r;
            uint4 v = make_uint4(0u, 0u, 0u, 0u);
            if (gr < N_NODES) v = A4[gr * 16 + c4];
            As4[r * 17 + c4] = v;
        }
    }
    __syncthreads();

    const int lane = tid & 31, w = tid >> 5;
    const int g = lane >> 2, t = lane & 3;
    const int wm = w >> 2;
    const int wn = w & 3;
    const uint2* Wt2 = (const uint2*)Wt;

    int cur = 0;
    for (int tile = blockIdx.x; tile < NB_GT; tile += gridDim.x) {
        const int m0 = tile * 64;
        const int ntile = tile + gridDim.x;

        uint4 pre[4];
        if (ntile < NB_GT) {
            const int nm0 = ntile * 64;
#pragma unroll
            for (int it = 0; it < 4; it++) {
                int idx = it * 256 + tid;
                int r   = idx >> 4;
                int c4  = idx & 15;
                int gr  = nm0 + r;
                pre[it] = make_uint4(0u, 0u, 0u, 0u);
                if (gr < N_NODES) pre[it] = A4[gr * 16 + c4];
            }
        }

        const uint32_t* As = cur ? Abuf1 : Abuf0;

        float acc[2][4][4];
#pragma unroll
        for (int i = 0; i < 2; i++)
#pragma unroll
            for (int j = 0; j < 4; j++)
#pragma unroll
                for (int q = 0; q < 4; q++) acc[i][j][q] = 0.0f;

#pragma unroll
        for (int ks = 0; ks < 8; ks++) {
            const int ka  = ks * 8 + t;
            const int ka2 = ka + 4;
            uint32_t a[2][4];
#pragma unroll
            for (int mt = 0; mt < 2; mt++) {
                int ra = (wm * 32 + mt * 16 + g) * AROW;
                int rb = ra + 8 * AROW;
                a[mt][0] = As[ra + ka];
                a[mt][1] = As[rb + ka];
                a[mt][2] = As[ra + ka2];
                a[mt][3] = As[rb + ka2];
            }
#pragma unroll
            for (int nt = 0; nt < 4; nt++) {
                int bn = (wn * 32 + nt * 8 + g) * 68;
                uint2 q0 = Wt2[bn + ka];
                uint2 q1 = Wt2[bn + ka2];
#pragma unroll
                for (int mt = 0; mt < 2; mt++) {
                    MMA_F16(acc[mt][nt], a[mt][0], a[mt][1], a[mt][2], a[mt][3], q0.x, q1.x);
                    MMA_F16(acc[mt][nt], a[mt][0], a[mt][1], a[mt][2], a[mt][3], q0.y, q1.y);
                }
            }
        }

#pragma unroll
        for (int mt = 0; mt < 2; mt++) {
            int grow0 = m0 + wm * 32 + mt * 16 + g;
            int grow1 = grow0 + 8;
#pragma unroll
            for (int nt = 0; nt < 4; nt++) {
                int c2 = wn * 16 + nt * 4 + t;
                if (grow0 < N_NODES)
                    g_xw2[grow0 * 64 + c2] = __floats2half2_rn(acc[mt][nt][0], acc[mt][nt][1]);
                if (grow1 < N_NODES)
                    g_xw2[grow1 * 64 + c2] = __floats2half2_rn(acc[mt][nt][2], acc[mt][nt][3]);
            }
        }

        if (ntile < NB_GT) {
            uint4* dst4 = (uint4*)(cur ? Abuf0 : Abuf1);
#pragma unroll
            for (int it = 0; it < 4; it++) {
                int idx = it * 256 + tid;
                int r   = idx >> 4;
                int c4  = idx & 15;
                dst4[r * 17 + c4] = pre[it];
            }
        }
        __syncthreads();
        cur ^= 1;
    }
}

// ---- edge aggregation v5: half-warp per edge, register-pipelined descriptors ----
__global__ void __launch_bounds__(256) agg_kernel(const float* __restrict__ bias) {
    int v = blockIdx.x * 8 + (threadIdx.x >> 5);
    if (v >= N_NODES) return;
    int lane = threadIdx.x & 31;
    int half = lane >> 4;
    int hl   = lane & 15;

    const uint4* xw = (const uint4*)g_xw2;
    float acc[8];
#pragma unroll
    for (int j = 0; j < 8; j++) acc[j] = 0.0f;

    int s = g_beg[v];
    int e = s + g_deg[v];
    int i = s + half;
    int2 epn = (i < e) ? g_epack[i] : make_int2(0, 0);
#pragma unroll 2
    for (; i < e; i += 2) {
        int2 ep = epn;
        int ni = i + 2;
        if (ni < e) epn = g_epack[ni];   // prefetch next descriptor; overlaps gather below
        float nn = __int_as_float(ep.y);
        uint4 p = xw[ep.x * 16 + hl];
        float2 f0 = __half22float2(*(__half2*)&p.x);
        float2 f1 = __half22float2(*(__half2*)&p.y);
        float2 f2 = __half22float2(*(__half2*)&p.z);
        float2 f3 = __half22float2(*(__half2*)&p.w);
        acc[0] += nn * f0.x; acc[1] += nn * f0.y;
        acc[2] += nn * f1.x; acc[3] += nn * f1.y;
        acc[4] += nn * f2.x; acc[5] += nn * f2.y;
        acc[6] += nn * f3.x; acc[7] += nn * f3.y;
    }
#pragma unroll
    for (int j = 0; j < 8; j++) acc[j] += __shfl_down_sync(~0u, acc[j], 16);

    if (half == 0) {
        float di = g_dinv[v];
        float sl = di * di;
        uint4 p = xw[v * 16 + hl];
        float2 f0 = __half22float2(*(__half2*)&p.x);
        float2 f1 = __half22float2(*(__half2*)&p.y);
        float2 f2 = __half22float2(*(__half2*)&p.z);
        float2 f3 = __half22float2(*(__half2*)&p.w);
        acc[0] += sl * f0.x; acc[1] += sl * f0.y;
        acc[2] += sl * f1.x; acc[3] += sl * f1.y;
        acc[4] += sl * f2.x; acc[5] += sl * f2.y;
        acc[6] += sl * f3.x; acc[7] += sl * f3.y;

        float4 b0 = ((const float4*)bias)[2 * hl];
        float4 b1 = ((const float4*)bias)[2 * hl + 1];
        acc[0] = fmaxf(acc[0] + b0.x, 0.0f);
        acc[1] = fmaxf(acc[1] + b0.y, 0.0f);
        acc[2] = fmaxf(acc[2] + b0.z, 0.0f);
        acc[3] = fmaxf(acc[3] + b0.w, 0.0f);
        acc[4] = fmaxf(acc[4] + b1.x, 0.0f);
        acc[5] = fmaxf(acc[5] + b1.y, 0.0f);
        acc[6] = fmaxf(acc[6] + b1.z, 0.0f);
        acc[7] = fmaxf(acc[7] + b1.w, 0.0f);

        __half2 o0 = __floats2half2_rn(acc[0], acc[1]);
        __half2 o1 = __floats2half2_rn(acc[2], acc[3]);
        __half2 o2 = __floats2half2_rn(acc[4], acc[5]);
        __half2 o3 = __floats2half2_rn(acc[6], acc[7]);
        ((uint4*)g_h16)[v * 16 + hl] =
            make_uint4(*(uint32_t*)&o0, *(uint32_t*)&o1, *(uint32_t*)&o2, *(uint32_t*)&o3);
    }
}

// ---------------- graph boundaries ----------------
__global__ void gptr_kernel(const int* __restrict__ batch) {
    int i = blockIdx.x * blockDim.x + threadIdx.x;
    if (i >= N_NODES) return;
    int b = batch[i];
    int p = (i == 0) ? -1 : batch[i - 1];
    for (int g = p + 1; g <= b; g++) g_gptr[g] = i;
    if (i == N_NODES - 1)
        for (int g = b + 1; g <= NGRAPH; g++) g_gptr[g] = N_NODES;
}

// ---------------- segment max with BN folded ----------------
__global__ void __launch_bounds__(64) segmax_kernel(const float* __restrict__ gamma,
                                                    const float* __restrict__ beta,
                                                    const float* __restrict__ mean,
                                                    const float* __restrict__ var) {
    int g = blockIdx.x;
    int j = threadIdx.x;
    float sc0 = gamma[2 * j]     * rsqrtf(var[2 * j]     + 1e-5f);
    float sc1 = gamma[2 * j + 1] * rsqrtf(var[2 * j + 1] + 1e-5f);
    float sh0 = beta[2 * j]     - mean[2 * j]     * sc0;
    float sh1 = beta[2 * j + 1] - mean[2 * j + 1] * sc1;
    float m0 = -FLT_MAX, m1 = -FLT_MAX;
    int s = g_gptr[g];
    int e = g_gptr[g + 1];
    for (int i = s; i < e; i++) {
        float2 f = __half22float2(g_h16[i * 64 + j]);
        m0 = fmaxf(m0, f.x * sc0 + sh0);
        m1 = fmaxf(m1, f.y * sc1 + sh1);
    }
    g_pool[g * 128 + 2 * j]     = m0;
    g_pool[g * 128 + 2 * j + 1] = m1;
}

// ---------------- MLP head ----------------
__global__ void __launch_bounds__(128) mlp_kernel(const float* __restrict__ lw1, const float* __restrict__ lb1,
                                                  const float* __restrict__ lw2, const float* __restrict__ lb2,
                                                  const float* __restrict__ lw3, const float* __restrict__ lb3,
                                                  float* __restrict__ out) {
    __shared__ float r1[128];
    __shared__ float r2[128];
    int g = blockIdx.x, t = threadIdx.x;
    r1[t] = g_pool[g * 128 + t];
    __syncthreads();

    float s = lb1[t];
#pragma unroll 8
    for (int k = 0; k < 128; k++) s += r1[k] * lw1[k * 128 + t];
    s = fmaxf(s, 0.0f);
    __syncthreads();
    r2[t] = s;
    __syncthreads();

    float s2 = 0.0f;
    if (t < 64) {
        s2 = lb2[t];
#pragma unroll 8
        for (int k = 0; k < 128; k++) s2 += r2[k] * lw2[k * 64 + t];
        s2 = fmaxf(s2, 0.0f);
    }
    __syncthreads();
    if (t < 64) r1[t] = s2;
    __syncthreads();

    if (t < NCLS) {
        float s3 = lb3[t];
#pragma unroll
        for (int k = 0; k < 64; k++) s3 += r1[k] * lw3[k * NCLS + t];
        out[g * NCLS + t] = s3;
    }
}

// ---------------- launch: fork-join over two streams ----------------
extern "C" void kernel_launch(void* const* d_in, const int* in_sizes, int n_in,
                              void* d_out, int out_size) {
    const float* x     = (const float*)d_in[0];
    const int*   ei    = (const int*)d_in[1];
    const int*   src   = ei;
    const int*   dst   = ei + N_EDGES;
    const int*   batch = (const int*)d_in[2];
    const float* W1 = (const float*)d_in[3];  const float* b1 = (const float*)d_in[4];
    const float* W2 = (const float*)d_in[5];  const float* b2 = (const float*)d_in[6];
    const float* W3 = (const float*)d_in[7];  const float* b3 = (const float*)d_in[8];
    const float* gamma = (const float*)d_in[9];
    const float* beta  = (const float*)d_in[10];
    const float* rmean = (const float*)d_in[11];
    const float* rvar  = (const float*)d_in[12];
    const float* lw1 = (const float*)d_in[13]; const float* lb1 = (const float*)d_in[14];
    const float* lw2 = (const float*)d_in[15]; const float* lb2 = (const float*)d_in[16];
    const float* lw3 = (const float*)d_in[17]; const float* lb3 = (const float*)d_in[18];
    float* out = (float*)d_out;

    const int NB_N = (N_NODES + 255) / 256;
    const int NB_E = (N_EDGES + 255) / 256;
    const int NB_A = (N_NODES + 7) / 8;
    const int NB_X = (N_NODES * 64 + 255) / 256;
    const int GEMM_SMEM = (2 * ATILE16 + WTILE) * 4;    // 104448 bytes

    cudaFuncSetAttribute(gemm_tc, cudaFuncAttributeMaxDynamicSharedMemorySize, GEMM_SMEM);

    cudaStream_t s2;
    cudaStreamCreateWithFlags(&s2, cudaStreamNonBlocking);
    cudaEvent_t evFork, evJoin;
    cudaEventCreateWithFlags(&evFork, cudaEventDisableTiming);
    cudaEventCreateWithFlags(&evJoin, cudaEventDisableTiming);

    cudaEventRecord(evFork, 0);
    cudaStreamWaitEvent(s2, evFork, 0);
    zero_kernel<<<NB_N, 256, 0, s2>>>();
    deg_kernel<<<NB_E, 256, 0, s2>>>(dst);
    scanfill_kernel<<<NPART, 256, 0, s2>>>();
    fill_kernel<<<NB_E, 256, 0, s2>>>(src, dst);
    gptr_kernel<<<NB_N, 256, 0, s2>>>(batch);
    cudaEventRecord(evJoin, s2);

    wsplit_kernel<<<dim3(8, 3), 256>>>(W1, W2, W3);
    x16_kernel<<<NB_X, 256>>>(x);
    gemm_tc<<<GEMM_GRID, 256, GEMM_SMEM>>>(0, 0);

    cudaStreamWaitEvent(0, evJoin, 0);

    agg_kernel<<<NB_A, 256>>>(b1);
    gemm_tc<<<GEMM_GRID, 256, GEMM_SMEM>>>(1, 1);
    agg_kernel<<<NB_A, 256>>>(b2);
    gemm_tc<<<GEMM_GRID, 256, GEMM_SMEM>>>(1, 2);
    agg_kernel<<<NB_A, 256>>>(b3);

    segmax_kernel<<<NGRAPH, 64>>>(gamma, beta, rmean, rvar);
    mlp_kernel<<<NGRAPH, 128>>>(lw1, lb1, lw2, lb2, lw3, lb3, out);

    cudaStreamDestroy(s2);
    cudaEventDestroy(evFork);
    cudaEventDestroy(evJoin);
}

// round 15
// speedup vs baseline: 1.0388x; 1.0388x over previous
#include <cuda_runtime.h>
#include <cuda_fp16.h>
#include <cstdint>
#include <math.h>
#include <float.h>

#define N_NODES 50000
#define N_EDGES 600000
#define NHID    128
#define NGRAPH  512
#define NCLS    10
#define NPART   ((N_NODES + 255) / 256)   // 196
#define WROW    136
#define WTILE   (128 * WROW)
#define AROW    68
#define ATILE16 (64 * AROW)
#define NB_GT   ((N_NODES + 63) / 64)      // 782 M tiles
#define GEMM_GRID 296

// ---------------- scratch ----------------
__device__ __half2  g_x16[N_NODES * 64];
__device__ __half2  g_xw2[N_NODES * 64];
__device__ __half2  g_h16[N_NODES * 64];
__device__ float    g_dinv[N_NODES];
__device__ int      g_deg [N_NODES];
__device__ int      g_beg [N_NODES];
__device__ int      g_fill[N_NODES];
__device__ int      g_total;
__device__ int2     g_epack[N_EDGES];
__device__ int      g_gptr[NGRAPH + 1];
__device__ float    g_pool[NGRAPH * NHID];
__device__ uint32_t g_wprep[3 * WTILE];

// ---------------- graph preprocessing ----------------
__global__ void zero_kernel() {
    int v = blockIdx.x * blockDim.x + threadIdx.x;
    if (v < N_NODES) g_deg[v] = 0;
    if (v == 0) g_total = 0;
}

__global__ void deg_kernel(const int* __restrict__ dst) {
    int e = blockIdx.x * blockDim.x + threadIdx.x;
    if (e < N_EDGES) atomicAdd(&g_deg[dst[e]], 1);
}

__global__ void __launch_bounds__(256) scanfill_kernel() {
    int i = blockIdx.x * 256 + threadIdx.x;
    int v = 0;
    if (i < N_NODES) {
        v = g_deg[i];
        g_dinv[i] = rsqrtf((float)v + 1.0f);
    }
    int lane = threadIdx.x & 31, w = threadIdx.x >> 5;
    int x = v;
    for (int o = 1; o < 32; o <<= 1) {
        int n = __shfl_up_sync(~0u, x, o);
        if (lane >= o) x += n;
    }
    __shared__ int ws[8];
    __shared__ int sbase;
    if (lane == 31) ws[w] = x;
    __syncthreads();
    if (w == 0 && lane < 8) {
        int s = ws[lane];
        for (int o = 1; o < 8; o <<= 1) {
            int n = __shfl_up_sync(0xffu, s, o);
            if (lane >= o) s += n;
        }
        ws[lane] = s;
    }
    __syncthreads();
    if (threadIdx.x == 0) sbase = atomicAdd(&g_total, ws[7]);
    __syncthreads();
    int off = x - v + ((w > 0) ? ws[w - 1] : 0) + sbase;
    if (i < N_NODES) {
        g_beg[i]  = off;
        g_fill[i] = off;
    }
}

__global__ void fill_kernel(const int* __restrict__ src, const int* __restrict__ dst) {
    int e = blockIdx.x * blockDim.x + threadIdx.x;
    if (e >= N_EDGES) return;
    int d = dst[e];
    int s = src[e];
    int pos = atomicAdd(&g_fill[d], 1);
    g_epack[pos] = make_int2(s, __float_as_int(g_dinv[s] * g_dinv[d]));
}

// ---------------- x -> fp16 ----------------
__global__ void __launch_bounds__(256) x16_kernel(const float* __restrict__ x) {
    int idx = blockIdx.x * 256 + threadIdx.x;
    if (idx < N_NODES * 64) {
        float2 f = ((const float2*)x)[idx];
        g_x16[idx] = __floats2half2_rn(f.x, f.y);
    }
}

// ---------------- fp16 split helpers ----------------
__device__ __forceinline__ uint32_t packh_hi(float a, float b, float& ra, float& rb) {
    __half h0 = __float2half_rn(a);
    __half h1 = __float2half_rn(b);
    ra = a - __half2float(h0);
    rb = b - __half2float(h1);
    __half2 p = __half2(h0, h1);
    return *(uint32_t*)&p;
}
__device__ __forceinline__ uint32_t packh_lo(float ra, float rb) {
    __half2 p = __half2(__float2half_rn(ra), __float2half_rn(rb));
    return *(uint32_t*)&p;
}
#define MMA_F16(C, A0, A1, A2, A3, B0, B1)                                         \
    asm volatile("mma.sync.aligned.m16n8k16.row.col.f32.f16.f16.f32 "              \
                 "{%0,%1,%2,%3}, {%4,%5,%6,%7}, {%8,%9}, {%0,%1,%2,%3};"           \
                 : "+f"(C[0]), "+f"(C[1]), "+f"(C[2]), "+f"(C[3])                  \
                 : "r"(A0), "r"(A1), "r"(A2), "r"(A3), "r"(B0), "r"(B1))

// ---------------- W pre-split ----------------
__global__ void __launch_bounds__(256) wsplit_kernel(const float* __restrict__ W1,
                                                     const float* __restrict__ W2,
                                                     const float* __restrict__ W3) {
    const float* W = (blockIdx.y == 0) ? W1 : (blockIdx.y == 1) ? W2 : W3;
    uint32_t* dst = g_wprep + blockIdx.y * WTILE;
    int base = blockIdx.x * 256 + threadIdx.x;
    for (int p = base; p < 4096; p += 2048) {
        int kp = p >> 6;
        int np = p & 63;
        int k = kp * 2, n = np * 2;
        float2 w0 = *(const float2*)(W + k * 128 + n);
        float2 w1 = *(const float2*)(W + (k + 1) * 128 + n);
        float r0, r1, r2, r3;
        uint32_t hA = packh_hi(w0.x, w1.x, r0, r1);
        uint32_t hB = packh_hi(w0.y, w1.y, r2, r3);
        *(uint2*)&dst[n * WROW + kp * 2]       = make_uint2(hA, packh_lo(r0, r1));
        *(uint2*)&dst[(n + 1) * WROW + kp * 2] = make_uint2(hB, packh_lo(r2, r3));
    }
}

// ---------------- persistent tensor-core GEMM, A dbuf + staged epilogue ---------
__global__ void __launch_bounds__(256, 2) gemm_tc(int use_gh, int layer) {
    extern __shared__ uint32_t sm[];
    uint32_t* Abuf0 = sm;
    uint32_t* Abuf1 = sm + ATILE16;
    uint32_t* Wt    = sm + 2 * ATILE16;
    const uint4* A4 = use_gh ? (const uint4*)g_h16 : (const uint4*)g_x16;
    const int tid = threadIdx.x;

    {
        const uint4* wp = (const uint4*)(g_wprep + layer * WTILE);
        uint4* Wt4 = (uint4*)Wt;
#pragma unroll
        for (int it = 0; it < 17; it++) {
            int idx = it * 256 + tid;
            if (idx < WTILE / 4) Wt4[idx] = wp[idx];
        }
    }
    {
        const int m0 = blockIdx.x * 64;
        uint4* As4 = (uint4*)Abuf0;
#pragma unroll
        for (int it = 0; it < 4; it++) {
            int idx = it * 256 + tid;
            int r   = idx >> 4;
            int c4  = idx & 15;
            int gr  = m0 + r;
            uint4 v = make_uint4(0u, 0u, 0u, 0u);
            if (gr < N_NODES) v = A4[gr * 16 + c4];
            As4[r * 17 + c4] = v;
        }
    }
    __syncthreads();

    const int lane = tid & 31, w = tid >> 5;
    const int g = lane >> 2, t = lane & 3;
    const int wm = w >> 2;
    const int wn = w & 3;
    const uint2* Wt2 = (const uint2*)Wt;

    int cur = 0;
    for (int tile = blockIdx.x; tile < NB_GT; tile += gridDim.x) {
        const int m0 = tile * 64;
        const int ntile = tile + gridDim.x;

        // prefetch next A tile into registers
        uint4 pre[4];
        if (ntile < NB_GT) {
            const int nm0 = ntile * 64;
#pragma unroll
            for (int it = 0; it < 4; it++) {
                int idx = it * 256 + tid;
                int r   = idx >> 4;
                int c4  = idx & 15;
                int gr  = nm0 + r;
                pre[it] = make_uint4(0u, 0u, 0u, 0u);
                if (gr < N_NODES) pre[it] = A4[gr * 16 + c4];
            }
        }

        uint32_t* AsC = cur ? Abuf1 : Abuf0;    // current (will be reused as staging)
        const uint32_t* As = AsC;

        float acc[2][4][4];
#pragma unroll
        for (int i = 0; i < 2; i++)
#pragma unroll
            for (int j = 0; j < 4; j++)
#pragma unroll
                for (int q = 0; q < 4; q++) acc[i][j][q] = 0.0f;

#pragma unroll
        for (int ks = 0; ks < 8; ks++) {
            const int ka  = ks * 8 + t;
            const int ka2 = ka + 4;
            uint32_t a[2][4];
#pragma unroll
            for (int mt = 0; mt < 2; mt++) {
                int ra = (wm * 32 + mt * 16 + g) * AROW;
                int rb = ra + 8 * AROW;
                a[mt][0] = As[ra + ka];
                a[mt][1] = As[rb + ka];
                a[mt][2] = As[ra + ka2];
                a[mt][3] = As[rb + ka2];
            }
#pragma unroll
            for (int nt = 0; nt < 4; nt++) {
                int bn = (wn * 32 + nt * 8 + g) * 68;
                uint2 q0 = Wt2[bn + ka];
                uint2 q1 = Wt2[bn + ka2];
#pragma unroll
                for (int mt = 0; mt < 2; mt++) {
                    MMA_F16(acc[mt][nt], a[mt][0], a[mt][1], a[mt][2], a[mt][3], q0.x, q1.x);
                    MMA_F16(acc[mt][nt], a[mt][0], a[mt][1], a[mt][2], a[mt][3], q0.y, q1.y);
                }
            }
        }

        // store prefetched tile into the OTHER buffer (free to write now)
        if (ntile < NB_GT) {
            uint4* dst4 = (uint4*)(cur ? Abuf0 : Abuf1);
#pragma unroll
            for (int it = 0; it < 4; it++) {
                int idx = it * 256 + tid;
                int r   = idx >> 4;
                int c4  = idx & 15;
                dst4[r * 17 + c4] = pre[it];
            }
        }
        __syncthreads();   // all warps done reading AsC; pre-stores done

        // --- staged epilogue: STS conflict-free, then coalesced STG.128 ---
#pragma unroll
        for (int mt = 0; mt < 2; mt++) {
            int r0 = wm * 32 + mt * 16 + g;
            int r1 = r0 + 8;
#pragma unroll
            for (int nt = 0; nt < 4; nt++) {
                int c2 = wn * 16 + nt * 4 + t;
                __half2 o0 = __floats2half2_rn(acc[mt][nt][0], acc[mt][nt][1]);
                __half2 o1 = __floats2half2_rn(acc[mt][nt][2], acc[mt][nt][3]);
                AsC[r0 * AROW + c2] = *(uint32_t*)&o0;
                AsC[r1 * AROW + c2] = *(uint32_t*)&o1;
            }
        }
        __syncthreads();
        {
            uint4* out4 = (uint4*)g_xw2;
#pragma unroll
            for (int it = 0; it < 4; it++) {
                int idx = it * 256 + tid;     // 1024 uint4
                int r   = idx >> 4;
                int c4  = idx & 15;
                uint4 v = *(uint4*)&AsC[r * AROW + c4 * 4];
                int gr = m0 + r;
                if (gr < N_NODES) out4[gr * 16 + c4] = v;
            }
        }
        __syncthreads();   // staging reads done before next-iter pre-store hits AsC
        cur ^= 1;
    }
}

// ---------------- edge aggregation v2: half-warp per edge row (LDG.128) --------
__global__ void __launch_bounds__(256) agg_kernel(const float* __restrict__ bias) {
    int v = blockIdx.x * 8 + (threadIdx.x >> 5);
    if (v >= N_NODES) return;
    int lane = threadIdx.x & 31;
    int half = lane >> 4;
    int hl   = lane & 15;

    const uint4* xw = (const uint4*)g_xw2;
    float acc[8];
#pragma unroll
    for (int j = 0; j < 8; j++) acc[j] = 0.0f;

    int s = g_beg[v];
    int e = s + g_deg[v];
#pragma unroll 4
    for (int i = s + half; i < e; i += 2) {
        int2 ep = g_epack[i];
        float nn = __int_as_float(ep.y);
        uint4 p = xw[ep.x * 16 + hl];
        float2 f0 = __half22float2(*(__half2*)&p.x);
        float2 f1 = __half22float2(*(__half2*)&p.y);
        float2 f2 = __half22float2(*(__half2*)&p.z);
        float2 f3 = __half22float2(*(__half2*)&p.w);
        acc[0] += nn * f0.x; acc[1] += nn * f0.y;
        acc[2] += nn * f1.x; acc[3] += nn * f1.y;
        acc[4] += nn * f2.x; acc[5] += nn * f2.y;
        acc[6] += nn * f3.x; acc[7] += nn * f3.y;
    }
#pragma unroll
    for (int j = 0; j < 8; j++) acc[j] += __shfl_down_sync(~0u, acc[j], 16);

    if (half == 0) {
        float di = g_dinv[v];
        float sl = di * di;
        uint4 p = xw[v * 16 + hl];
        float2 f0 = __half22float2(*(__half2*)&p.x);
        float2 f1 = __half22float2(*(__half2*)&p.y);
        float2 f2 = __half22float2(*(__half2*)&p.z);
        float2 f3 = __half22float2(*(__half2*)&p.w);
        acc[0] += sl * f0.x; acc[1] += sl * f0.y;
        acc[2] += sl * f1.x; acc[3] += sl * f1.y;
        acc[4] += sl * f2.x; acc[5] += sl * f2.y;
        acc[6] += sl * f3.x; acc[7] += sl * f3.y;

        float4 b0 = ((const float4*)bias)[2 * hl];
        float4 b1 = ((const float4*)bias)[2 * hl + 1];
        acc[0] = fmaxf(acc[0] + b0.x, 0.0f);
        acc[1] = fmaxf(acc[1] + b0.y, 0.0f);
        acc[2] = fmaxf(acc[2] + b0.z, 0.0f);
        acc[3] = fmaxf(acc[3] + b0.w, 0.0f);
        acc[4] = fmaxf(acc[4] + b1.x, 0.0f);
        acc[5] = fmaxf(acc[5] + b1.y, 0.0f);
        acc[6] = fmaxf(acc[6] + b1.z, 0.0f);
        acc[7] = fmaxf(acc[7] + b1.w, 0.0f);

        __half2 o0 = __floats2half2_rn(acc[0], acc[1]);
        __half2 o1 = __floats2half2_rn(acc[2], acc[3]);
        __half2 o2 = __floats2half2_rn(acc[4], acc[5]);
        __half2 o3 = __floats2half2_rn(acc[6], acc[7]);
        ((uint4*)g_h16)[v * 16 + hl] =
            make_uint4(*(uint32_t*)&o0, *(uint32_t*)&o1, *(uint32_t*)&o2, *(uint32_t*)&o3);
    }
}

// ---------------- graph boundaries ----------------
__global__ void gptr_kernel(const int* __restrict__ batch) {
    int i = blockIdx.x * blockDim.x + threadIdx.x;
    if (i >= N_NODES) return;
    int b = batch[i];
    int p = (i == 0) ? -1 : batch[i - 1];
    for (int g = p + 1; g <= b; g++) g_gptr[g] = i;
    if (i == N_NODES - 1)
        for (int g = b + 1; g <= NGRAPH; g++) g_gptr[g] = N_NODES;
}

// ---------------- segment max with BN folded ----------------
__global__ void __launch_bounds__(64) segmax_kernel(const float* __restrict__ gamma,
                                                    const float* __restrict__ beta,
                                                    const float* __restrict__ mean,
                                                    const float* __restrict__ var) {
    int g = blockIdx.x;
    int j = threadIdx.x;
    float sc0 = gamma[2 * j]     * rsqrtf(var[2 * j]     + 1e-5f);
    float sc1 = gamma[2 * j + 1] * rsqrtf(var[2 * j + 1] + 1e-5f);
    float sh0 = beta[2 * j]     - mean[2 * j]     * sc0;
    float sh1 = beta[2 * j + 1] - mean[2 * j + 1] * sc1;
    float m0 = -FLT_MAX, m1 = -FLT_MAX;
    int s = g_gptr[g];
    int e = g_gptr[g + 1];
    for (int i = s; i < e; i++) {
        float2 f = __half22float2(g_h16[i * 64 + j]);
        m0 = fmaxf(m0, f.x * sc0 + sh0);
        m1 = fmaxf(m1, f.y * sc1 + sh1);
    }
    g_pool[g * 128 + 2 * j]     = m0;
    g_pool[g * 128 + 2 * j + 1] = m1;
}

// ---------------- MLP head ----------------
__global__ void __launch_bounds__(128) mlp_kernel(const float* __restrict__ lw1, const float* __restrict__ lb1,
                                                  const float* __restrict__ lw2, const float* __restrict__ lb2,
                                                  const float* __restrict__ lw3, const float* __restrict__ lb3,
                                                  float* __restrict__ out) {
    __shared__ float r1[128];
    __shared__ float r2[128];
    int g = blockIdx.x, t = threadIdx.x;
    r1[t] = g_pool[g * 128 + t];
    __syncthreads();

    float s = lb1[t];
#pragma unroll 8
    for (int k = 0; k < 128; k++) s += r1[k] * lw1[k * 128 + t];
    s = fmaxf(s, 0.0f);
    __syncthreads();
    r2[t] = s;
    __syncthreads();

    float s2 = 0.0f;
    if (t < 64) {
        s2 = lb2[t];
#pragma unroll 8
        for (int k = 0; k < 128; k++) s2 += r2[k] * lw2[k * 64 + t];
        s2 = fmaxf(s2, 0.0f);
    }
    __syncthreads();
    if (t < 64) r1[t] = s2;
    __syncthreads();

    if (t < NCLS) {
        float s3 = lb3[t];
#pragma unroll
        for (int k = 0; k < 64; k++) s3 += r1[k] * lw3[k * NCLS + t];
        out[g * NCLS + t] = s3;
    }
}

// ---------------- launch: fork-join over two streams ----------------
extern "C" void kernel_launch(void* const* d_in, const int* in_sizes, int n_in,
                              void* d_out, int out_size) {
    const float* x     = (const float*)d_in[0];
    const int*   ei    = (const int*)d_in[1];
    const int*   src   = ei;
    const int*   dst   = ei + N_EDGES;
    const int*   batch = (const int*)d_in[2];
    const float* W1 = (const float*)d_in[3];  const float* b1 = (const float*)d_in[4];
    const float* W2 = (const float*)d_in[5];  const float* b2 = (const float*)d_in[6];
    const float* W3 = (const float*)d_in[7];  const float* b3 = (const float*)d_in[8];
    const float* gamma = (const float*)d_in[9];
    const float* beta  = (const float*)d_in[10];
    const float* rmean = (const float*)d_in[11];
    const float* rvar  = (const float*)d_in[12];
    const float* lw1 = (const float*)d_in[13]; const float* lb1 = (const float*)d_in[14];
    const float* lw2 = (const float*)d_in[15]; const float* lb2 = (const float*)d_in[16];
    const float* lw3 = (const float*)d_in[17]; const float* lb3 = (const float*)d_in[18];
    float* out = (float*)d_out;

    const int NB_N = (N_NODES + 255) / 256;
    const int NB_E = (N_EDGES + 255) / 256;
    const int NB_A = (N_NODES + 7) / 8;
    const int NB_X = (N_NODES * 64 + 255) / 256;
    const int GEMM_SMEM = (2 * ATILE16 + WTILE) * 4;    // 104448 bytes

    cudaFuncSetAttribute(gemm_tc, cudaFuncAttributeMaxDynamicSharedMemorySize, GEMM_SMEM);

    cudaStream_t s2;
    cudaStreamCreateWithFlags(&s2, cudaStreamNonBlocking);
    cudaEvent_t evFork, evJoin;
    cudaEventCreateWithFlags(&evFork, cudaEventDisableTiming);
    cudaEventCreateWithFlags(&evJoin, cudaEventDisableTiming);

    cudaEventRecord(evFork, 0);
    cudaStreamWaitEvent(s2, evFork, 0);
    zero_kernel<<<NB_N, 256, 0, s2>>>();
    deg_kernel<<<NB_E, 256, 0, s2>>>(dst);
    scanfill_kernel<<<NPART, 256, 0, s2>>>();
    fill_kernel<<<NB_E, 256, 0, s2>>>(src, dst);
    gptr_kernel<<<NB_N, 256, 0, s2>>>(batch);
    cudaEventRecord(evJoin, s2);

    wsplit_kernel<<<dim3(8, 3), 256>>>(W1, W2, W3);
    x16_kernel<<<NB_X, 256>>>(x);
    gemm_tc<<<GEMM_GRID, 256, GEMM_SMEM>>>(0, 0);

    cudaStreamWaitEvent(0, evJoin, 0);

    agg_kernel<<<NB_A, 256>>>(b1);
    gemm_tc<<<GEMM_GRID, 256, GEMM_SMEM>>>(1, 1);
    agg_kernel<<<NB_A, 256>>>(b2);
    gemm_tc<<<GEMM_GRID, 256, GEMM_SMEM>>>(1, 2);
    agg_kernel<<<NB_A, 256>>>(b3);

    segmax_kernel<<<NGRAPH, 64>>>(gamma, beta, rmean, rvar);
    mlp_kernel<<<NGRAPH, 128>>>(lw1, lb1, lw2, lb2, lw3, lb3, out);

    cudaStreamDestroy(s2);
    cudaEventDestroy(evFork);
    cudaEventDestroy(evJoin);
}